// round 2
// baseline (speedup 1.0000x reference)
#include <cuda_runtime.h>

#define NQ      12
#define DIM     4096      // 2^12 amplitudes
#define THREADS 256
#define DIN     768
#define H1      256
#define NOUT    28

// SMEM layout swizzle: XOR low 4 float2-index bits with bits 7..4.
// Makes all three 4-bit fusion groups bank-conflict-free.
__device__ __forceinline__ int SW(int i) { return i ^ ((i >> 4) & 15); }

// Apply 4 fused single-qubit complex gates (bits SH+3..SH) to the statevector.
// Each thread owns one 16-amplitude register tile; one SMEM round-trip total.
template<int SH>
__device__ __forceinline__ void fused4_pass(float2* st, const float2 (*G)[4], int wb)
{
    const int tid  = threadIdx.x;
    const int low  = tid & ((1 << SH) - 1);
    const int base = ((tid >> SH) << (SH + 4)) | low;
    float2 a[16];
    #pragma unroll
    for (int k = 0; k < 16; k++) a[k] = st[SW(base | (k << SH))];
    #pragma unroll
    for (int j = 0; j < 4; j++) {
        const int gb = 3 - j;                  // wire wb+j lives on local bit 3-j
        const float2 u00 = G[wb + j][0], u01 = G[wb + j][1];
        const float2 u10 = G[wb + j][2], u11 = G[wb + j][3];
        #pragma unroll
        for (int k = 0; k < 16; k++) {
            if (k & (1 << gb)) continue;       // compile-time pruned
            const int k1 = k | (1 << gb);
            const float2 p = a[k], q = a[k1];
            float2 r0, r1;
            r0.x = u00.x*p.x - u00.y*p.y + u01.x*q.x - u01.y*q.y;
            r0.y = u00.x*p.y + u00.y*p.x + u01.x*q.y + u01.y*q.x;
            r1.x = u10.x*p.x - u10.y*p.y + u11.x*q.x - u11.y*q.y;
            r1.y = u10.x*p.y + u10.y*p.x + u11.x*q.y + u11.y*q.x;
            a[k] = r0; a[k1] = r1;
        }
    }
    #pragma unroll
    for (int k = 0; k < 16; k++) st[SW(base | (k << SH))] = a[k];
}

// CNOT(ctrl bit pc, tgt bit pt): swap amplitudes with ctrl=1 across tgt.
__device__ __forceinline__ void cnot_pass(float2* st, int pc, int pt)
{
    const int plo = pc < pt ? pc : pt;
    const int phb = pc < pt ? pt : pc;
    for (int i = threadIdx.x; i < 1024; i += THREADS) {
        int lo   = i & ((1 << plo) - 1);
        int mid  = (i >> plo) & ((1 << (phb - plo - 1)) - 1);
        int high = i >> (phb - 1);
        int idx  = (high << (phb + 1)) | (mid << (plo + 1)) | lo | (1 << pc);
        int idx2 = idx | (1 << pt);
        float2 t = st[SW(idx)];
        st[SW(idx)]  = st[SW(idx2)];
        st[SW(idx2)] = t;
    }
}

__global__ __launch_bounds__(THREADS, 3)
void hybrid_fused_kernel(const float* __restrict__ x,
                         const float* __restrict__ proj_w,
                         const float* __restrict__ proj_b,
                         const float* __restrict__ ln_w,
                         const float* __restrict__ ln_b,
                         const float* __restrict__ qw,     // (3,12,3)
                         const float* __restrict__ h1w,    // (256,12)
                         const float* __restrict__ h1b,
                         const float* __restrict__ h2w,    // (28,256)
                         const float* __restrict__ h2b,
                         float* __restrict__ out)          // (B,28)
{
    __shared__ float2 st[DIM];          // statevector (swizzled), 32 KB
    __shared__ float2 gmat[36][4];      // Rot matrices (batch-invariant)
    __shared__ float2 cg[NQ][4];        // layer-0 Rot*RY combined (per sample)
    __shared__ int    scol[NQ];         // columns of last-CNOT-ring linear map S
    __shared__ int    SL[64], SH8[64];  // S(j) = SL[j&63] ^ SH8[j>>6]
    __shared__ float  hvec[NQ];
    __shared__ float  zred[NQ];
    __shared__ float  zbuf[H1];
    __shared__ float  lnstats[2];

    const int tid  = threadIdx.x;
    const int lane = tid & 31;
    const int warp = tid >> 5;
    const int s    = blockIdx.x;

    // ---- projection: h[w] = tanh(dot(x_row, proj_w[w]) + proj_b[w]) ----
    const float* xr = x + s * DIN;
    for (int w = warp; w < NQ; w += 8) {
        const float* pw = proj_w + w * DIN;
        float acc = 0.f;
        for (int j = lane; j < DIN; j += 32) acc = fmaf(xr[j], pw[j], acc);
        #pragma unroll
        for (int o = 16; o; o >>= 1) acc += __shfl_down_sync(0xffffffffu, acc, o);
        if (lane == 0) hvec[w] = tanhf(acc + proj_b[w]);
    }

    // ---- Rot gate matrices: Rot(phi,th,om) = RZ(om) RY(th) RZ(phi) ----
    if (tid < 36) {
        const int base = tid * 3;               // gate tid = l*12 + w
        float phi = qw[base], th = qw[base + 1], om = qw[base + 2];
        float stt, ct;  sincosf(0.5f * th, &stt, &ct);
        float sa, ca;   sincosf(0.5f * (phi + om), &sa, &ca);
        float sb, cb;   sincosf(0.5f * (phi - om), &sb, &cb);
        gmat[tid][0] = make_float2( ca * ct,  -sa * ct);
        gmat[tid][1] = make_float2(-cb * stt, -sb * stt);
        gmat[tid][2] = make_float2( cb * stt, -sb * stt);
        gmat[tid][3] = make_float2( ca * ct,   sa * ct);
    }

    // ---- last-layer CNOT ring (r=3) as GF(2)-linear map S: basis columns ----
    if (tid == 0) {
        #pragma unroll
        for (int b = 0; b < NQ; b++) {
            int v = 1 << b;
            for (int w = NQ - 1; w >= 0; w--) {  // psi'[j] = psi[T0(T1(...T11(j)))]
                int pc = 11 - w, pt = 11 - ((w + 3) % NQ);
                v ^= ((v >> pc) & 1) << pt;
            }
            scol[b] = v;
        }
    }
    if (tid < NQ) zred[tid] = 0.f;

    // ---- init statevector ----
    for (int i = tid; i < DIM; i += THREADS) st[i] = make_float2(0.f, 0.f);
    __syncthreads();

    if (tid == 0) {
        st[0] = make_float2(1.f, 0.f);           // SW(0) == 0
        float mu = 0.f;
        #pragma unroll
        for (int w = 0; w < NQ; w++) mu += hvec[w];
        mu *= (1.f / NQ);
        float var = 0.f;
        #pragma unroll
        for (int w = 0; w < NQ; w++) { float d = hvec[w] - mu; var += d * d; }
        lnstats[0] = mu;
        lnstats[1] = rsqrtf(var * (1.f / NQ) + 1e-5f);
    }
    // S-map LUTs
    if (tid < 64) {
        int v = 0;
        #pragma unroll
        for (int b = 0; b < 6; b++) if (tid & (1 << b)) v ^= scol[b];
        SL[tid] = v;
    } else if (tid < 128) {
        int t = tid - 64, v = 0;
        #pragma unroll
        for (int b = 0; b < 6; b++) if (t & (1 << b)) v ^= scol[6 + b];
        SH8[t] = v;
    }
    __syncthreads();

    // ---- fold AngleEmbedding RY into layer-0 Rot: cg = Rot * RY ----
    if (tid < NQ) {
        float v = (hvec[tid] - lnstats[0]) * lnstats[1] * ln_w[tid] + ln_b[tid];
        float sn, c;  sincosf(0.5f * v, &sn, &c);
        float2 u00 = gmat[tid][0], u01 = gmat[tid][1];
        float2 u10 = gmat[tid][2], u11 = gmat[tid][3];
        cg[tid][0] = make_float2(u00.x*c + u01.x*sn,  u00.y*c + u01.y*sn);
        cg[tid][1] = make_float2(-u00.x*sn + u01.x*c, -u00.y*sn + u01.y*c);
        cg[tid][2] = make_float2(u10.x*c + u11.x*sn,  u10.y*c + u11.y*sn);
        cg[tid][3] = make_float2(-u10.x*sn + u11.x*c, -u10.y*sn + u11.y*c);
    }
    __syncthreads();

    // ---- layer 0: (RY+Rot) fused, then CNOT ring r=1 ----
    fused4_pass<8>(st, cg, 0);  __syncthreads();
    fused4_pass<4>(st, cg, 4);  __syncthreads();
    fused4_pass<0>(st, cg, 8);  __syncthreads();
    #pragma unroll 1
    for (int w = 0; w < NQ; w++) {
        cnot_pass(st, 11 - w, 11 - ((w + 1) % NQ));
        __syncthreads();
    }

    // ---- layer 1: Rot, then CNOT ring r=2 ----
    fused4_pass<8>(st, gmat + 12, 0);  __syncthreads();
    fused4_pass<4>(st, gmat + 12, 4);  __syncthreads();
    fused4_pass<0>(st, gmat + 12, 8);  __syncthreads();
    #pragma unroll 1
    for (int w = 0; w < NQ; w++) {
        cnot_pass(st, 11 - w, 11 - ((w + 2) % NQ));
        __syncthreads();
    }

    // ---- layer 2: Rot; CNOT ring r=3 folded into the probs gather ----
    fused4_pass<8>(st, gmat + 24, 0);  __syncthreads();
    fused4_pass<4>(st, gmat + 24, 4);  __syncthreads();
    fused4_pass<0>(st, gmat + 24, 8);  __syncthreads();

    // ---- PauliZ expectations: psi_final[j] = st[S(j)] ----
    float acc[NQ];
    #pragma unroll
    for (int w = 0; w < NQ; w++) acc[w] = 0.f;
    #pragma unroll
    for (int r16 = 0; r16 < 16; r16++) {
        const int j = tid + (r16 << 8);
        const int sidx = SL[j & 63] ^ SH8[j >> 6];
        const float2 aa = st[SW(sidx)];
        const float p = aa.x * aa.x + aa.y * aa.y;
        #pragma unroll
        for (int w = 0; w < NQ; w++)
            acc[w] += ((j >> (11 - w)) & 1) ? -p : p;
    }
    #pragma unroll
    for (int w = 0; w < NQ; w++) {
        float v = acc[w];
        #pragma unroll
        for (int o = 16; o; o >>= 1) v += __shfl_down_sync(0xffffffffu, v, o);
        if (lane == 0) atomicAdd(&zred[w], v);
    }
    __syncthreads();

    // ---- MLP head ----
    {
        float a = h1b[tid];
        const float* wrow = h1w + tid * NQ;
        #pragma unroll
        for (int k = 0; k < NQ; k++) a = fmaf(zred[k], wrow[k], a);
        zbuf[tid] = fmaxf(a, 0.f);
    }
    __syncthreads();

    for (int o = warp; o < NOUT; o += 8) {
        const float* wrow = h2w + o * H1;
        float a = 0.f;
        for (int k = lane; k < H1; k += 32) a = fmaf(zbuf[k], wrow[k], a);
        #pragma unroll
        for (int off = 16; off; off >>= 1) a += __shfl_down_sync(0xffffffffu, a, off);
        if (lane == 0) out[s * NOUT + o] = a + h2b[o];
    }
}

extern "C" void kernel_launch(void* const* d_in, const int* in_sizes, int n_in,
                              void* d_out, int out_size)
{
    const float* x      = (const float*)d_in[0];
    const float* proj_w = (const float*)d_in[1];
    const float* proj_b = (const float*)d_in[2];
    const float* ln_w   = (const float*)d_in[3];
    const float* ln_b   = (const float*)d_in[4];
    const float* q_w    = (const float*)d_in[5];
    const float* h1_w   = (const float*)d_in[6];
    const float* h1_b   = (const float*)d_in[7];
    const float* h2_w   = (const float*)d_in[8];
    const float* h2_b   = (const float*)d_in[9];
    float* out = (float*)d_out;

    const int B = in_sizes[0] / DIN;   // 512
    hybrid_fused_kernel<<<B, THREADS>>>(x, proj_w, proj_b, ln_w, ln_b, q_w,
                                        h1_w, h1_b, h2_w, h2_b, out);
}

// round 3
// speedup vs baseline: 2.1900x; 2.1900x over previous
#include <cuda_runtime.h>

#define NQ      12
#define DIM     4096      // 2^12 amplitudes
#define THREADS 256
#define DIN     768
#define H1      256
#define NOUT    28

// SMEM layout swizzle: XOR low 4 float2-index bits with bits 7..4.
// Makes all three 4-bit fusion groups bank-conflict-free.
__device__ __forceinline__ int SW(int i) { return i ^ ((i >> 4) & 15); }

// 4 fused single-qubit complex gates applied to a 16-amplitude register tile.
__device__ __forceinline__ void apply4(float2 a[16], const float2 (*G)[4], int wb)
{
    #pragma unroll
    for (int j = 0; j < 4; j++) {
        const int gb = 3 - j;                  // wire wb+j lives on local bit 3-j
        const float2 u00 = G[wb + j][0], u01 = G[wb + j][1];
        const float2 u10 = G[wb + j][2], u11 = G[wb + j][3];
        #pragma unroll
        for (int k = 0; k < 16; k++) {
            if (k & (1 << gb)) continue;       // compile-time pruned
            const int k1 = k | (1 << gb);
            const float2 p = a[k], q = a[k1];
            float2 r0, r1;
            r0.x = u00.x*p.x - u00.y*p.y + u01.x*q.x - u01.y*q.y;
            r0.y = u00.x*p.y + u00.y*p.x + u01.x*q.y + u01.y*q.x;
            r1.x = u10.x*p.x - u10.y*p.y + u11.x*q.x - u11.y*q.y;
            r1.y = u10.x*p.y + u10.y*p.x + u11.x*q.y + u11.y*q.x;
            a[k] = r0; a[k1] = r1;
        }
    }
}

// Standard in-place pass on bits SH+3..SH.
template<int SH>
__device__ __forceinline__ void fused4_pass(float2* st, const float2 (*G)[4], int wb)
{
    const int tid  = threadIdx.x;
    const int low  = tid & ((1 << SH) - 1);
    const int base = ((tid >> SH) << (SH + 4)) | low;
    float2 a[16];
    #pragma unroll
    for (int k = 0; k < 16; k++) a[k] = st[SW(base | (k << SH))];
    apply4(a, G, wb);
    #pragma unroll
    for (int k = 0; k < 16; k++) st[SW(base | (k << SH))] = a[k];
}

// Layer-transition pass (bits 11..8): loads through the CNOT-ring linear map
//   a[k] = psi_pre[f(tid | k<<8)] = st[ CT[tid] ^ CK[k] ],
// barrier (all permuted loads done before any in-place store), gates, store standard.
__device__ __forceinline__ void fused4_gather_pass(float2* st, const float2 (*G)[4], int wb,
                                                   const int* __restrict__ CT,
                                                   const int* __restrict__ CK)
{
    const int tid = threadIdx.x;
    const int cb  = CT[tid];
    float2 a[16];
    #pragma unroll
    for (int k = 0; k < 16; k++) a[k] = st[SW(cb ^ CK[k])];
    __syncthreads();
    apply4(a, G, wb);
    #pragma unroll
    for (int k = 0; k < 16; k++) st[SW(tid | (k << 8))] = a[k];
}

// Composed CNOT-ring index map for range r: psi'[j] = psi[f_r(j)].
__device__ __forceinline__ int ring_map(int v, int r)
{
    #pragma unroll
    for (int w = NQ - 1; w >= 0; w--) {
        int pc = 11 - w, pt = 11 - ((w + r) % NQ);
        v ^= ((v >> pc) & 1) << pt;
    }
    return v;
}

__global__ __launch_bounds__(THREADS, 3)
void hybrid_fused_kernel(const float* __restrict__ x,
                         const float* __restrict__ proj_w,
                         const float* __restrict__ proj_b,
                         const float* __restrict__ ln_w,
                         const float* __restrict__ ln_b,
                         const float* __restrict__ qw,     // (3,12,3)
                         const float* __restrict__ h1w,    // (256,12)
                         const float* __restrict__ h1b,
                         const float* __restrict__ h2w,    // (28,256)
                         const float* __restrict__ h2b,
                         float* __restrict__ out)          // (B,28)
{
    __shared__ float2 st[DIM];          // statevector (swizzled), 32 KB
    __shared__ float2 gmat[36][4];      // Rot matrices (batch-invariant)
    __shared__ float2 cg[NQ][4];        // layer-0 Rot*RY combined (per sample)
    __shared__ int    C1T[256], C2T[256];   // ring maps on low 8 bits
    __shared__ int    CK1[16],  CK2[16];    // ring maps on bits 11..8
    __shared__ int    SL[64], SH8[64];      // r=3 ring: S(j) = SL[j&63] ^ SH8[j>>6]
    __shared__ float  hvec[NQ];
    __shared__ float  zred[NQ];
    __shared__ float  zbuf[H1];
    __shared__ float  lnstats[2];

    const int tid  = threadIdx.x;
    const int lane = tid & 31;
    const int warp = tid >> 5;
    const int s    = blockIdx.x;

    // ---- projection: h[w] = tanh(dot(x_row, proj_w[w]) + proj_b[w]) ----
    const float* xr = x + s * DIN;
    for (int w = warp; w < NQ; w += 8) {
        const float* pw = proj_w + w * DIN;
        float acc = 0.f;
        for (int j = lane; j < DIN; j += 32) acc = fmaf(xr[j], pw[j], acc);
        #pragma unroll
        for (int o = 16; o; o >>= 1) acc += __shfl_down_sync(0xffffffffu, acc, o);
        if (lane == 0) hvec[w] = tanhf(acc + proj_b[w]);
    }

    // ---- Rot gate matrices: Rot(phi,th,om) = RZ(om) RY(th) RZ(phi) ----
    if (tid < 36) {
        const int base = tid * 3;               // gate tid = l*12 + w
        float phi = qw[base], th = qw[base + 1], om = qw[base + 2];
        float stt, ct;  sincosf(0.5f * th, &stt, &ct);
        float sa, ca;   sincosf(0.5f * (phi + om), &sa, &ca);
        float sb, cb;   sincosf(0.5f * (phi - om), &sb, &cb);
        gmat[tid][0] = make_float2( ca * ct,  -sa * ct);
        gmat[tid][1] = make_float2(-cb * stt, -sb * stt);
        gmat[tid][2] = make_float2( cb * stt, -sb * stt);
        gmat[tid][3] = make_float2( ca * ct,   sa * ct);
    }

    // ---- CNOT-ring LUTs (weights-independent, parallel across threads) ----
    C1T[tid] = ring_map(tid, 1);
    C2T[tid] = ring_map(tid, 2);
    if (tid < 16) {
        CK1[tid] = ring_map(tid << 8, 1);
        CK2[tid] = ring_map(tid << 8, 2);
    } else if (tid < 80) {                      // r=3 map for the Z gather
        int t = tid - 16;
        SL[t]  = ring_map(t, 3);
    } else if (tid < 144) {
        int t = tid - 80;
        SH8[t] = ring_map(t << 6, 3) ^ ring_map(0, 3); // ring_map(0)=0; keep form
    }
    if (tid < NQ) zred[tid] = 0.f;

    // ---- init statevector ----
    for (int i = tid; i < DIM; i += THREADS) st[i] = make_float2(0.f, 0.f);
    __syncthreads();

    if (tid == 0) {
        st[0] = make_float2(1.f, 0.f);           // SW(0) == 0
        float mu = 0.f;
        #pragma unroll
        for (int w = 0; w < NQ; w++) mu += hvec[w];
        mu *= (1.f / NQ);
        float var = 0.f;
        #pragma unroll
        for (int w = 0; w < NQ; w++) { float d = hvec[w] - mu; var += d * d; }
        lnstats[0] = mu;
        lnstats[1] = rsqrtf(var * (1.f / NQ) + 1e-5f);
    }
    __syncthreads();

    // ---- fold AngleEmbedding RY into layer-0 Rot: cg = Rot * RY ----
    if (tid < NQ) {
        float v = (hvec[tid] - lnstats[0]) * lnstats[1] * ln_w[tid] + ln_b[tid];
        float sn, c;  sincosf(0.5f * v, &sn, &c);
        float2 u00 = gmat[tid][0], u01 = gmat[tid][1];
        float2 u10 = gmat[tid][2], u11 = gmat[tid][3];
        cg[tid][0] = make_float2(u00.x*c + u01.x*sn,  u00.y*c + u01.y*sn);
        cg[tid][1] = make_float2(-u00.x*sn + u01.x*c, -u00.y*sn + u01.y*c);
        cg[tid][2] = make_float2(u10.x*c + u11.x*sn,  u10.y*c + u11.y*sn);
        cg[tid][3] = make_float2(-u10.x*sn + u11.x*c, -u10.y*sn + u11.y*c);
    }
    __syncthreads();

    // ---- layer 0: (RY+Rot) fused; CNOT ring r=1 deferred into next load ----
    fused4_pass<8>(st, cg, 0);  __syncthreads();
    fused4_pass<4>(st, cg, 4);  __syncthreads();
    fused4_pass<0>(st, cg, 8);  __syncthreads();

    // ---- layer 1: first pass gathers through r=1 ring; r=2 deferred ----
    fused4_gather_pass(st, gmat + 12, 0, C1T, CK1);  __syncthreads();
    fused4_pass<4>(st, gmat + 12, 4);                __syncthreads();
    fused4_pass<0>(st, gmat + 12, 8);                __syncthreads();

    // ---- layer 2: first pass gathers through r=2 ring; r=3 deferred to Z ----
    fused4_gather_pass(st, gmat + 24, 0, C2T, CK2);  __syncthreads();
    fused4_pass<4>(st, gmat + 24, 4);                __syncthreads();
    fused4_pass<0>(st, gmat + 24, 8);                __syncthreads();

    // ---- PauliZ expectations: psi_final[j] = st[S(j)] (r=3 ring folded) ----
    float acc[NQ];
    #pragma unroll
    for (int w = 0; w < NQ; w++) acc[w] = 0.f;
    #pragma unroll
    for (int r16 = 0; r16 < 16; r16++) {
        const int j = tid + (r16 << 8);
        const int sidx = SL[j & 63] ^ SH8[j >> 6];
        const float2 aa = st[SW(sidx)];
        const float p = aa.x * aa.x + aa.y * aa.y;
        #pragma unroll
        for (int w = 0; w < NQ; w++)
            acc[w] += ((j >> (11 - w)) & 1) ? -p : p;
    }
    #pragma unroll
    for (int w = 0; w < NQ; w++) {
        float v = acc[w];
        #pragma unroll
        for (int o = 16; o; o >>= 1) v += __shfl_down_sync(0xffffffffu, v, o);
        if (lane == 0) atomicAdd(&zred[w], v);
    }
    __syncthreads();

    // ---- MLP head ----
    {
        float a = h1b[tid];
        const float* wrow = h1w + tid * NQ;
        #pragma unroll
        for (int k = 0; k < NQ; k++) a = fmaf(zred[k], wrow[k], a);
        zbuf[tid] = fmaxf(a, 0.f);
    }
    __syncthreads();

    for (int o = warp; o < NOUT; o += 8) {
        const float* wrow = h2w + o * H1;
        float a = 0.f;
        for (int k = lane; k < H1; k += 32) a = fmaf(zbuf[k], wrow[k], a);
        #pragma unroll
        for (int off = 16; off; off >>= 1) a += __shfl_down_sync(0xffffffffu, a, off);
        if (lane == 0) out[s * NOUT + o] = a + h2b[o];
    }
}

extern "C" void kernel_launch(void* const* d_in, const int* in_sizes, int n_in,
                              void* d_out, int out_size)
{
    const float* x      = (const float*)d_in[0];
    const float* proj_w = (const float*)d_in[1];
    const float* proj_b = (const float*)d_in[2];
    const float* ln_w   = (const float*)d_in[3];
    const float* ln_b   = (const float*)d_in[4];
    const float* q_w    = (const float*)d_in[5];
    const float* h1_w   = (const float*)d_in[6];
    const float* h1_b   = (const float*)d_in[7];
    const float* h2_w   = (const float*)d_in[8];
    const float* h2_b   = (const float*)d_in[9];
    float* out = (float*)d_out;

    const int B = in_sizes[0] / DIN;   // 512
    hybrid_fused_kernel<<<B, THREADS>>>(x, proj_w, proj_b, ln_w, ln_b, q_w,
                                        h1_w, h1_b, h2_w, h2_b, out);
}